// round 5
// baseline (speedup 1.0000x reference)
#include <cuda_runtime.h>
#include <cstdint>

// Problem constants
#define BSZ   8
#define CDIM  384
#define NTOK  1024
#define NH    12
#define DH    32
static constexpr float SCALE = 0.17677669529663687f;  // 32^-0.5

typedef unsigned long long ull;

// Packed f32x2 helpers (sm_103a: 2x fp32 FMA throughput vs scalar FFMA)
#define PACK2(d, lo, hi) \
    asm("mov.b64 %0, {%1, %2};" : "=l"(d) : "r"(__float_as_uint(lo)), "r"(__float_as_uint(hi)))
#define UNPACK2(lo, hi, s) \
    { unsigned _ulo, _uhi; \
      asm("mov.b64 {%0, %1}, %2;" : "=r"(_ulo), "=r"(_uhi) : "l"(s)); \
      lo = __uint_as_float(_ulo); hi = __uint_as_float(_uhi); }
#define FMA2(acc, a, b) \
    asm("fma.rn.f32x2 %0, %1, %2, %0;" : "+l"(acc) : "l"(a), "l"(b))
#define MUL2(acc, m) \
    asm("mul.rn.f32x2 %0, %0, %1;" : "+l"(acc) : "l"(m))

__device__ __forceinline__ ull dupf(float v) {
    ull r;
    asm("mov.b64 %0, {%1, %1};" : "=l"(r) : "r"(__float_as_uint(v)));
    return r;
}

// Scratch (device globals; no allocations allowed)
static __device__ float g_q[(size_t)BSZ * NH * NTOK * DH];
static __device__ float g_k[(size_t)BSZ * NH * NTOK * DH];
static __device__ float g_v[(size_t)BSZ * NH * NTOK * DH];
static __device__ float g_o[(size_t)BSZ * NTOK * CDIM];

// ---------------------------------------------------------------------------
// Kernel 1: QKV projection.  out[b,m,o] = sum_c x[b,c,m] * Wqkv[o,c]
// 128x128 tile, BK=16. B tile stored as duplicated f32 pairs (no PACK2 in loop).
// ---------------------------------------------------------------------------
__global__ __launch_bounds__(256) void qkv_gemm(const float* __restrict__ x,
                                                const float* __restrict__ W) {
    int b  = blockIdx.z;
    int m0 = blockIdx.x * 128;
    int o0 = blockIdx.y * 128;
    __shared__ float As[16][128];
    __shared__ ull   Bs2[16][128];   // dup pairs
    int t  = threadIdx.x;
    int tx = t & 15, ty = t >> 4;

    ull acc2[4][8];
#pragma unroll
    for (int i = 0; i < 4; i++)
#pragma unroll
        for (int j = 0; j < 8; j++) acc2[i][j] = 0ull;

    const float* xb = x + (size_t)b * CDIM * NTOK;

    for (int k0 = 0; k0 < CDIM; k0 += 16) {
        {
            int kk = t >> 5;
            int m4 = (t & 31) * 4;
            const float* src = xb + (size_t)(k0 + kk) * NTOK + m0 + m4;
            *(float4*)&As[kk][m4]     = *(const float4*)src;
            *(float4*)&As[kk + 8][m4] = *(const float4*)(src + 8 * NTOK);
        }
        {
            int oo = t >> 1;
            int k8 = (t & 1) * 8;
            const float* ws = W + (size_t)(o0 + oo) * CDIM + k0 + k8;
            float4 w0 = *(const float4*)ws;
            float4 w1 = *(const float4*)(ws + 4);
            Bs2[k8 + 0][oo] = dupf(w0.x); Bs2[k8 + 1][oo] = dupf(w0.y);
            Bs2[k8 + 2][oo] = dupf(w0.z); Bs2[k8 + 3][oo] = dupf(w0.w);
            Bs2[k8 + 4][oo] = dupf(w1.x); Bs2[k8 + 5][oo] = dupf(w1.y);
            Bs2[k8 + 6][oo] = dupf(w1.z); Bs2[k8 + 7][oo] = dupf(w1.w);
        }
        __syncthreads();
#pragma unroll
        for (int kk = 0; kk < 16; kk++) {
            ulonglong2 a01 = *(const ulonglong2*)&As[kk][ty * 4];
            ulonglong2 a23 = *(const ulonglong2*)&As[kk][64 + ty * 4];
            ull a2[4] = {a01.x, a01.y, a23.x, a23.y};
            ulonglong2 b01 = *(const ulonglong2*)&Bs2[kk][tx * 4];
            ulonglong2 b23 = *(const ulonglong2*)&Bs2[kk][tx * 4 + 2];
            ulonglong2 b45 = *(const ulonglong2*)&Bs2[kk][64 + tx * 4];
            ulonglong2 b67 = *(const ulonglong2*)&Bs2[kk][64 + tx * 4 + 2];
            ull b2[8] = {b01.x, b01.y, b23.x, b23.y, b45.x, b45.y, b67.x, b67.y};
#pragma unroll
            for (int i = 0; i < 4; i++)
#pragma unroll
                for (int j = 0; j < 8; j++) FMA2(acc2[i][j], a2[i], b2[j]);
        }
        __syncthreads();
    }

#pragma unroll
    for (int i2 = 0; i2 < 4; i2++) {
        float rl[8], rh[8];
#pragma unroll
        for (int j = 0; j < 8; j++) UNPACK2(rl[j], rh[j], acc2[i2][j]);
#pragma unroll
        for (int half = 0; half < 2; half++) {
            int m = m0 + (i2 >> 1) * 64 + ty * 4 + (i2 & 1) * 2 + half;
            float* r = half ? rh : rl;
#pragma unroll
            for (int gj = 0; gj < 2; gj++) {
                int o   = o0 + gj * 64 + tx * 4;
                int s   = o / CDIM;
                int rem = o - s * CDIM;
                int h   = rem >> 5;
                int d   = rem & 31;
                float* dst = (s == 0) ? g_q : (s == 1) ? g_k : g_v;
                size_t idx = (((size_t)b * NH + h) * NTOK + m) * DH + d;
                *(float4*)&dst[idx] = make_float4(r[gj*4+0], r[gj*4+1],
                                                  r[gj*4+2], r[gj*4+3]);
            }
        }
    }
}

// ---------------------------------------------------------------------------
// Kernel 2: flash attention v3 — Q tile 128, K chunk 64, 256 threads.
// Per-thread: S 8q x 4k, O 8q x 2d. K/V staged as duplicated pairs (no PACK2).
// Dynamic smem: Qs 16K + Ks2 16.5K + Vs2 17K + Ps 33K = 84.5 KB, 2 CTAs/SM.
// ---------------------------------------------------------------------------
#define QS(d, q)  Qs[(d) * 128 + (q)]
#define KS2(d, k) Ks2[(d) * 66 + (k)]
#define VS2(k, d) Vs2[(k) * 34 + (d)]
#define PS(k, q)  Ps[(k) * 132 + (q)]
#define FLASH_SMEM (32*128*4 + 32*66*8 + 64*34*8 + 64*132*4)

__global__ __launch_bounds__(256, 2) void flash_attn3() {
    extern __shared__ float smem[];
    float* Qs  = smem;
    ull*   Ks2 = (ull*)(smem + 32 * 128);
    ull*   Vs2 = Ks2 + 32 * 66;
    float* Ps  = (float*)(Vs2 + 64 * 34);

    int b  = blockIdx.z;
    int h  = blockIdx.y;
    int q0 = blockIdx.x * 128;
    int t  = threadIdx.x;
    int tx = t & 15, ty = t >> 4;

    size_t base = ((size_t)(b * NH + h) * NTOK) * DH;
    const float4* gq4 = (const float4*)(g_q + base);
    const float4* gk4 = (const float4*)(g_k + base);
    const float4* gv4 = (const float4*)(g_v + base);

    // Load Q tile (128 q x 32 d) transposed + scaled
#pragma unroll
    for (int i = 0; i < 4; i++) {
        int f4 = t + i * 256;             // 0..1023
        int q  = f4 >> 3, d4 = f4 & 7;
        float4 v = gq4[q0 * 8 + f4];
        QS(d4*4+0, q) = v.x * SCALE; QS(d4*4+1, q) = v.y * SCALE;
        QS(d4*4+2, q) = v.z * SCALE; QS(d4*4+3, q) = v.w * SCALE;
    }

    float mr[8], lr[8];
#pragma unroll
    for (int r = 0; r < 8; r++) { mr[r] = -1e30f; lr[r] = 0.f; }
    ull O2[4][2];
#pragma unroll
    for (int i = 0; i < 4; i++) { O2[i][0] = 0ull; O2[i][1] = 0ull; }

    for (int c = 0; c < 16; c++) {
        __syncthreads();   // (A) prior chunk's PV done with Ks2/Vs2/Ps
#pragma unroll
        for (int i = 0; i < 2; i++) {
            int f4 = t + i * 256;          // 0..511
            int k  = f4 >> 3, d4 = f4 & 7;
            float4 kv = gk4[c * 512 + f4];
            KS2(d4*4+0, k) = dupf(kv.x); KS2(d4*4+1, k) = dupf(kv.y);
            KS2(d4*4+2, k) = dupf(kv.z); KS2(d4*4+3, k) = dupf(kv.w);
            float4 vv = gv4[c * 512 + f4];
            ulonglong2 p0, p1;
            p0.x = dupf(vv.x); p0.y = dupf(vv.y);
            p1.x = dupf(vv.z); p1.y = dupf(vv.w);
            *(ulonglong2*)&VS2(k, d4*4)     = p0;
            *(ulonglong2*)&VS2(k, d4*4 + 2) = p1;
        }
        __syncthreads();   // (B)

        // ---- S GEMM: S[8q][4k] over d=32 ----
        ull S2[4][4];
#pragma unroll
        for (int i = 0; i < 4; i++)
#pragma unroll
            for (int j = 0; j < 4; j++) S2[i][j] = 0ull;
#pragma unroll 8
        for (int d = 0; d < 32; d++) {
            ulonglong2 a01 = *(const ulonglong2*)&QS(d, ty * 8);
            ulonglong2 a23 = *(const ulonglong2*)&QS(d, ty * 8 + 4);
            ulonglong2 b01 = *(const ulonglong2*)&KS2(d, tx * 4);
            ulonglong2 b23 = *(const ulonglong2*)&KS2(d, tx * 4 + 2);
            ull a2[4] = {a01.x, a01.y, a23.x, a23.y};
            ull b2[4] = {b01.x, b01.y, b23.x, b23.y};
#pragma unroll
            for (int i = 0; i < 4; i++)
#pragma unroll
                for (int j = 0; j < 4; j++) FMA2(S2[i][j], a2[i], b2[j]);
        }

        // ---- online softmax (8 rows per thread) ----
        float sl[4][4], sh[4][4];
#pragma unroll
        for (int i = 0; i < 4; i++)
#pragma unroll
            for (int j = 0; j < 4; j++) UNPACK2(sl[i][j], sh[i][j], S2[i][j]);

        float mc[8];
#pragma unroll
        for (int i = 0; i < 4; i++) {
            mc[2*i+0] = fmaxf(fmaxf(sl[i][0], sl[i][1]), fmaxf(sl[i][2], sl[i][3]));
            mc[2*i+1] = fmaxf(fmaxf(sh[i][0], sh[i][1]), fmaxf(sh[i][2], sh[i][3]));
        }
#pragma unroll
        for (int r = 0; r < 8; r++)
#pragma unroll
            for (int off = 8; off; off >>= 1)
                mc[r] = fmaxf(mc[r], __shfl_xor_sync(0xffffffffu, mc[r], off));

#pragma unroll
        for (int i = 0; i < 4; i++) {
            float mn0 = fmaxf(mr[2*i+0], mc[2*i+0]);
            float mn1 = fmaxf(mr[2*i+1], mc[2*i+1]);
            float a0 = __expf(mr[2*i+0] - mn0);
            float a1 = __expf(mr[2*i+1] - mn1);
            mr[2*i+0] = mn0; mr[2*i+1] = mn1;
            lr[2*i+0] *= a0; lr[2*i+1] *= a1;
            ull al2;
            PACK2(al2, a0, a1);
            MUL2(O2[i][0], al2); MUL2(O2[i][1], al2);
        }

#pragma unroll
        for (int i = 0; i < 4; i++)
#pragma unroll
            for (int j = 0; j < 4; j++) {
                float pl = __expf(sl[i][j] - mr[2*i+0]);
                float ph = __expf(sh[i][j] - mr[2*i+1]);
                lr[2*i+0] += pl; lr[2*i+1] += ph;
                sl[i][j] = pl; sh[i][j] = ph;
            }
#pragma unroll
        for (int j = 0; j < 4; j++) {
            *(float4*)&PS(tx*4+j, ty*8)     =
                make_float4(sl[0][j], sh[0][j], sl[1][j], sh[1][j]);
            *(float4*)&PS(tx*4+j, ty*8 + 4) =
                make_float4(sl[2][j], sh[2][j], sl[3][j], sh[3][j]);
        }

        __syncthreads();   // (C) Ps visible

        // ---- PV GEMM: O[8q][2d] += P[8q][64k] * V[64k][2d] ----
#pragma unroll 8
        for (int k = 0; k < 64; k++) {
            ulonglong2 a01 = *(const ulonglong2*)&PS(k, ty * 8);
            ulonglong2 a23 = *(const ulonglong2*)&PS(k, ty * 8 + 4);
            ulonglong2 bv  = *(const ulonglong2*)&VS2(k, tx * 2);
            FMA2(O2[0][0], a01.x, bv.x); FMA2(O2[0][1], a01.x, bv.y);
            FMA2(O2[1][0], a01.y, bv.x); FMA2(O2[1][1], a01.y, bv.y);
            FMA2(O2[2][0], a23.x, bv.x); FMA2(O2[2][1], a23.x, bv.y);
            FMA2(O2[3][0], a23.y, bv.x); FMA2(O2[3][1], a23.y, bv.y);
        }
    }

    // reduce l across tx (disjoint 4-key slices per chunk)
#pragma unroll
    for (int r = 0; r < 8; r++)
#pragma unroll
        for (int off = 8; off; off >>= 1)
            lr[r] += __shfl_xor_sync(0xffffffffu, lr[r], off);

#pragma unroll
    for (int i = 0; i < 4; i++) {
        float o0l, o0h, o1l, o1h;
        UNPACK2(o0l, o0h, O2[i][0]);
        UNPACK2(o1l, o1h, O2[i][1]);
        float inv0 = 1.f / lr[2*i+0];
        float inv1 = 1.f / lr[2*i+1];
        int qa = q0 + ty * 8 + 2*i;
        float* dst0 = &g_o[((size_t)b * NTOK + qa)     * CDIM + h * DH + tx * 2];
        float* dst1 = &g_o[((size_t)b * NTOK + qa + 1) * CDIM + h * DH + tx * 2];
        *(float2*)dst0 = make_float2(o0l * inv0, o1l * inv0);
        *(float2*)dst1 = make_float2(o0h * inv1, o1h * inv1);
    }
}

// ---------------------------------------------------------------------------
// Kernel 3: output projection + bias, transposed store. Dup-pair B tile.
// ---------------------------------------------------------------------------
__global__ __launch_bounds__(256) void proj_gemm(const float* __restrict__ W,
                                                 const float* __restrict__ bias,
                                                 float* __restrict__ out) {
    int b  = blockIdx.z;
    int m0 = blockIdx.x * 128;
    int o0 = blockIdx.y * 128;
    __shared__ float As[16][128];
    __shared__ ull   Bs2[16][128];
    int t  = threadIdx.x;
    int tx = t & 15, ty = t >> 4;

    ull acc2[4][8];   // m-pairs (tx dim) x 8 o (ty dim)
#pragma unroll
    for (int i = 0; i < 4; i++)
#pragma unroll
        for (int j = 0; j < 8; j++) acc2[i][j] = 0ull;

    const float* ao = g_o + (size_t)b * NTOK * CDIM;

    for (int k0 = 0; k0 < CDIM; k0 += 16) {
        {
            int mm = t >> 1;
            int k8 = (t & 1) * 8;
            const float* src = ao + (size_t)(m0 + mm) * CDIM + k0 + k8;
            float4 a0 = *(const float4*)src;
            float4 a1 = *(const float4*)(src + 4);
            As[k8 + 0][mm] = a0.x; As[k8 + 1][mm] = a0.y;
            As[k8 + 2][mm] = a0.z; As[k8 + 3][mm] = a0.w;
            As[k8 + 4][mm] = a1.x; As[k8 + 5][mm] = a1.y;
            As[k8 + 6][mm] = a1.z; As[k8 + 7][mm] = a1.w;

            const float* ws = W + (size_t)(o0 + mm) * CDIM + k0 + k8;
            float4 w0 = *(const float4*)ws;
            float4 w1 = *(const float4*)(ws + 4);
            Bs2[k8 + 0][mm] = dupf(w0.x); Bs2[k8 + 1][mm] = dupf(w0.y);
            Bs2[k8 + 2][mm] = dupf(w0.z); Bs2[k8 + 3][mm] = dupf(w0.w);
            Bs2[k8 + 4][mm] = dupf(w1.x); Bs2[k8 + 5][mm] = dupf(w1.y);
            Bs2[k8 + 6][mm] = dupf(w1.z); Bs2[k8 + 7][mm] = dupf(w1.w);
        }
        __syncthreads();
#pragma unroll
        for (int kk = 0; kk < 16; kk++) {
            ulonglong2 a01 = *(const ulonglong2*)&As[kk][tx * 4];
            ulonglong2 a23 = *(const ulonglong2*)&As[kk][64 + tx * 4];
            ull a2[4] = {a01.x, a01.y, a23.x, a23.y};
            ulonglong2 b01 = *(const ulonglong2*)&Bs2[kk][ty * 4];
            ulonglong2 b23 = *(const ulonglong2*)&Bs2[kk][ty * 4 + 2];
            ulonglong2 b45 = *(const ulonglong2*)&Bs2[kk][64 + ty * 4];
            ulonglong2 b67 = *(const ulonglong2*)&Bs2[kk][64 + ty * 4 + 2];
            ull b2[8] = {b01.x, b01.y, b23.x, b23.y, b45.x, b45.y, b67.x, b67.y};
#pragma unroll
            for (int i = 0; i < 4; i++)
#pragma unroll
                for (int j = 0; j < 8; j++) FMA2(acc2[i][j], a2[i], b2[j]);
        }
        __syncthreads();
    }

#pragma unroll
    for (int gj = 0; gj < 2; gj++)
#pragma unroll
        for (int j = 0; j < 4; j++) {
            int J = gj * 4 + j;
            int o = o0 + gj * 64 + ty * 4 + j;
            float bv = bias[o];
            float* dstrow = out + ((size_t)b * CDIM + o) * NTOK + m0;
#pragma unroll
            for (int gi = 0; gi < 2; gi++) {
                float v0l, v0h, v1l, v1h;
                UNPACK2(v0l, v0h, acc2[gi*2 + 0][J]);
                UNPACK2(v1l, v1h, acc2[gi*2 + 1][J]);
                int ml = gi * 64 + tx * 4;
                *(float4*)&dstrow[ml] = make_float4(v0l + bv, v0h + bv,
                                                    v1l + bv, v1h + bv);
            }
        }
}

// ---------------------------------------------------------------------------
extern "C" void kernel_launch(void* const* d_in, const int* in_sizes, int n_in,
                              void* d_out, int out_size) {
    const float* x     = (const float*)d_in[0];
    const float* Wqkv  = (const float*)d_in[1];
    const float* Wproj = (const float*)d_in[2];
    const float* bproj = (const float*)d_in[3];
    float* out = (float*)d_out;

    cudaFuncSetAttribute(flash_attn3,
                         cudaFuncAttributeMaxDynamicSharedMemorySize, FLASH_SMEM);

    qkv_gemm<<<dim3(8, 9, 8), 256>>>(x, Wqkv);
    flash_attn3<<<dim3(8, 12, 8), 256, FLASH_SMEM>>>();
    proj_gemm<<<dim3(8, 3, 8), 256>>>(Wproj, bproj, out);
}

// round 6
// speedup vs baseline: 1.5435x; 1.5435x over previous
#include <cuda_runtime.h>
#include <cstdint>

// Problem constants
#define BSZ   8
#define CDIM  384
#define NTOK  1024
#define NH    12
#define DH    32
static constexpr float SCALE = 0.17677669529663687f;  // 32^-0.5

typedef unsigned long long ull;

// Packed f32x2 helpers (sm_103a: 2x fp32 FMA throughput vs scalar FFMA)
#define PACK2(d, lo, hi) \
    asm("mov.b64 %0, {%1, %2};" : "=l"(d) : "r"(__float_as_uint(lo)), "r"(__float_as_uint(hi)))
#define UNPACK2(lo, hi, s) \
    { unsigned _ulo, _uhi; \
      asm("mov.b64 {%0, %1}, %2;" : "=r"(_ulo), "=r"(_uhi) : "l"(s)); \
      lo = __uint_as_float(_ulo); hi = __uint_as_float(_uhi); }
#define FMA2(acc, a, b) \
    asm("fma.rn.f32x2 %0, %1, %2, %0;" : "+l"(acc) : "l"(a), "l"(b))
#define MUL2(acc, m) \
    asm("mul.rn.f32x2 %0, %0, %1;" : "+l"(acc) : "l"(m))

// Scratch (device globals; no allocations allowed)
static __device__ float g_q[(size_t)BSZ * NH * NTOK * DH];
static __device__ float g_k[(size_t)BSZ * NH * NTOK * DH];
static __device__ float g_v[(size_t)BSZ * NH * NTOK * DH];
static __device__ float g_o[(size_t)BSZ * NTOK * CDIM];

// ---------------------------------------------------------------------------
// Kernel 1: QKV projection (R4 version — plain smem, PACK2 in loop).
// out[b,m,o] = sum_c x[b,c,m] * Wqkv[o,c]; 128x128 tile, BK=16, 256 threads.
// ---------------------------------------------------------------------------
__global__ __launch_bounds__(256) void qkv_gemm(const float* __restrict__ x,
                                                const float* __restrict__ W) {
    int b  = blockIdx.z;
    int m0 = blockIdx.x * 128;
    int o0 = blockIdx.y * 128;
    __shared__ float As[16][128];
    __shared__ float Bs[16][128];
    int t  = threadIdx.x;
    int tx = t & 15, ty = t >> 4;

    ull acc2[4][8];
#pragma unroll
    for (int i = 0; i < 4; i++)
#pragma unroll
        for (int j = 0; j < 8; j++) acc2[i][j] = 0ull;

    const float* xb = x + (size_t)b * CDIM * NTOK;

    for (int k0 = 0; k0 < CDIM; k0 += 16) {
        {
            int kk = t >> 5;
            int m4 = (t & 31) * 4;
            const float* src = xb + (size_t)(k0 + kk) * NTOK + m0 + m4;
            *(float4*)&As[kk][m4]     = *(const float4*)src;
            *(float4*)&As[kk + 8][m4] = *(const float4*)(src + 8 * NTOK);
        }
        {
            int oo = t >> 1;
            int k8 = (t & 1) * 8;
            const float* ws = W + (size_t)(o0 + oo) * CDIM + k0 + k8;
            float4 w0 = *(const float4*)ws;
            float4 w1 = *(const float4*)(ws + 4);
            Bs[k8 + 0][oo] = w0.x; Bs[k8 + 1][oo] = w0.y;
            Bs[k8 + 2][oo] = w0.z; Bs[k8 + 3][oo] = w0.w;
            Bs[k8 + 4][oo] = w1.x; Bs[k8 + 5][oo] = w1.y;
            Bs[k8 + 6][oo] = w1.z; Bs[k8 + 7][oo] = w1.w;
        }
        __syncthreads();
#pragma unroll
        for (int kk = 0; kk < 16; kk++) {
            ulonglong2 a01 = *(const ulonglong2*)&As[kk][ty * 4];
            ulonglong2 a23 = *(const ulonglong2*)&As[kk][64 + ty * 4];
            ull a2[4] = {a01.x, a01.y, a23.x, a23.y};
            float4 b0 = *(const float4*)&Bs[kk][tx * 4];
            float4 b1 = *(const float4*)&Bs[kk][64 + tx * 4];
            ull b2[8];
            PACK2(b2[0], b0.x, b0.x); PACK2(b2[1], b0.y, b0.y);
            PACK2(b2[2], b0.z, b0.z); PACK2(b2[3], b0.w, b0.w);
            PACK2(b2[4], b1.x, b1.x); PACK2(b2[5], b1.y, b1.y);
            PACK2(b2[6], b1.z, b1.z); PACK2(b2[7], b1.w, b1.w);
#pragma unroll
            for (int i = 0; i < 4; i++)
#pragma unroll
                for (int j = 0; j < 8; j++) FMA2(acc2[i][j], a2[i], b2[j]);
        }
        __syncthreads();
    }

#pragma unroll
    for (int i2 = 0; i2 < 4; i2++) {
        float rl[8], rh[8];
#pragma unroll
        for (int j = 0; j < 8; j++) UNPACK2(rl[j], rh[j], acc2[i2][j]);
#pragma unroll
        for (int half = 0; half < 2; half++) {
            int m = m0 + (i2 >> 1) * 64 + ty * 4 + (i2 & 1) * 2 + half;
            float* r = half ? rh : rl;
#pragma unroll
            for (int gj = 0; gj < 2; gj++) {
                int o   = o0 + gj * 64 + tx * 4;
                int s   = o / CDIM;
                int rem = o - s * CDIM;
                int h   = rem >> 5;
                int d   = rem & 31;
                float* dst = (s == 0) ? g_q : (s == 1) ? g_k : g_v;
                size_t idx = (((size_t)b * NH + h) * NTOK + m) * DH + d;
                *(float4*)&dst[idx] = make_float4(r[gj*4+0], r[gj*4+1],
                                                  r[gj*4+2], r[gj*4+3]);
            }
        }
    }
}

// ---------------------------------------------------------------------------
// Kernel 2: flash attention v4 — Q tile 128, K chunk 64, 256 threads.
// Per-thread: S 8q x 4k, O 8q x 2d. Plain smem (no dup), PACK2 amortized.
// Smem: Qs 16.9K + Ks 8.7K + Vs 9.2K + Ps 33.8K = 67 KB, 2 CTAs/SM.
// ---------------------------------------------------------------------------
#define QS(d, q)  Qs[(d) * 132 + (q)]
#define KS(d, k)  Ks[(d) * 68 + (k)]
#define VS(k, d)  Vs[(k) * 36 + (d)]
#define PS(k, q)  Ps[(k) * 132 + (q)]
#define FLASH_SMEM ((32*132 + 32*68 + 64*36 + 64*132) * 4)

__global__ __launch_bounds__(256, 2) void flash_attn4() {
    extern __shared__ float smem[];
    float* Qs = smem;
    float* Ks = Qs + 32 * 132;
    float* Vs = Ks + 32 * 68;
    float* Ps = Vs + 64 * 36;

    int b  = blockIdx.z;
    int h  = blockIdx.y;
    int q0 = blockIdx.x * 128;
    int t  = threadIdx.x;
    int tx = t & 15, ty = t >> 4;

    size_t base = ((size_t)(b * NH + h) * NTOK) * DH;
    const float4* gq4 = (const float4*)(g_q + base);
    const float4* gk4 = (const float4*)(g_k + base);
    const float4* gv4 = (const float4*)(g_v + base);

    // Load Q tile (128 q x 32 d) transposed + scaled
#pragma unroll
    for (int i = 0; i < 4; i++) {
        int f4 = t + i * 256;             // 0..1023
        int q  = f4 >> 3, d4 = f4 & 7;
        float4 v = gq4[q0 * 8 + f4];
        QS(d4*4+0, q) = v.x * SCALE; QS(d4*4+1, q) = v.y * SCALE;
        QS(d4*4+2, q) = v.z * SCALE; QS(d4*4+3, q) = v.w * SCALE;
    }

    float mr[8], lr[8];
#pragma unroll
    for (int r = 0; r < 8; r++) { mr[r] = -1e30f; lr[r] = 0.f; }
    ull O2[4][2];
#pragma unroll
    for (int i = 0; i < 4; i++) { O2[i][0] = 0ull; O2[i][1] = 0ull; }

    for (int c = 0; c < 16; c++) {
        __syncthreads();   // (A) prior chunk's PV done with Ks/Vs/Ps
#pragma unroll
        for (int i = 0; i < 2; i++) {
            int f4 = t + i * 256;          // 0..511
            int k  = f4 >> 3, d4 = f4 & 7;
            float4 kv = gk4[c * 512 + f4];
            KS(d4*4+0, k) = kv.x; KS(d4*4+1, k) = kv.y;
            KS(d4*4+2, k) = kv.z; KS(d4*4+3, k) = kv.w;
            *(float4*)&VS(k, d4*4) = gv4[c * 512 + f4];
        }
        __syncthreads();   // (B)

        // ---- S GEMM: S[8q][4k] over d=32 ----
        ull S2[4][4];
#pragma unroll
        for (int i = 0; i < 4; i++)
#pragma unroll
            for (int j = 0; j < 4; j++) S2[i][j] = 0ull;
#pragma unroll 8
        for (int d = 0; d < 32; d++) {
            ulonglong2 a01 = *(const ulonglong2*)&QS(d, ty * 8);
            ulonglong2 a23 = *(const ulonglong2*)&QS(d, ty * 8 + 4);
            float4 kv = *(const float4*)&KS(d, tx * 4);
            ull a2[4] = {a01.x, a01.y, a23.x, a23.y};
            ull b2[4];
            PACK2(b2[0], kv.x, kv.x); PACK2(b2[1], kv.y, kv.y);
            PACK2(b2[2], kv.z, kv.z); PACK2(b2[3], kv.w, kv.w);
#pragma unroll
            for (int i = 0; i < 4; i++)
#pragma unroll
                for (int j = 0; j < 4; j++) FMA2(S2[i][j], a2[i], b2[j]);
        }

        // ---- online softmax (8 rows per thread) ----
        float sl[4][4], sh[4][4];
#pragma unroll
        for (int i = 0; i < 4; i++)
#pragma unroll
            for (int j = 0; j < 4; j++) UNPACK2(sl[i][j], sh[i][j], S2[i][j]);

        float mc[8];
#pragma unroll
        for (int i = 0; i < 4; i++) {
            mc[2*i+0] = fmaxf(fmaxf(sl[i][0], sl[i][1]), fmaxf(sl[i][2], sl[i][3]));
            mc[2*i+1] = fmaxf(fmaxf(sh[i][0], sh[i][1]), fmaxf(sh[i][2], sh[i][3]));
        }
#pragma unroll
        for (int r = 0; r < 8; r++)
#pragma unroll
            for (int off = 8; off; off >>= 1)
                mc[r] = fmaxf(mc[r], __shfl_xor_sync(0xffffffffu, mc[r], off));

#pragma unroll
        for (int i = 0; i < 4; i++) {
            float mn0 = fmaxf(mr[2*i+0], mc[2*i+0]);
            float mn1 = fmaxf(mr[2*i+1], mc[2*i+1]);
            float a0 = __expf(mr[2*i+0] - mn0);
            float a1 = __expf(mr[2*i+1] - mn1);
            mr[2*i+0] = mn0; mr[2*i+1] = mn1;
            lr[2*i+0] *= a0; lr[2*i+1] *= a1;
            ull al2;
            PACK2(al2, a0, a1);
            MUL2(O2[i][0], al2); MUL2(O2[i][1], al2);
        }

#pragma unroll
        for (int i = 0; i < 4; i++)
#pragma unroll
            for (int j = 0; j < 4; j++) {
                float pl = __expf(sl[i][j] - mr[2*i+0]);
                float ph = __expf(sh[i][j] - mr[2*i+1]);
                lr[2*i+0] += pl; lr[2*i+1] += ph;
                sl[i][j] = pl; sh[i][j] = ph;
            }
#pragma unroll
        for (int j = 0; j < 4; j++) {
            *(float4*)&PS(tx*4+j, ty*8)     =
                make_float4(sl[0][j], sh[0][j], sl[1][j], sh[1][j]);
            *(float4*)&PS(tx*4+j, ty*8 + 4) =
                make_float4(sl[2][j], sh[2][j], sl[3][j], sh[3][j]);
        }

        __syncthreads();   // (C) Ps visible

        // ---- PV GEMM: O[8q][2d] += P[8q][64k] * V[64k][2d] ----
#pragma unroll 8
        for (int k = 0; k < 64; k++) {
            ulonglong2 a01 = *(const ulonglong2*)&PS(k, ty * 8);
            ulonglong2 a23 = *(const ulonglong2*)&PS(k, ty * 8 + 4);
            float2 vv = *(const float2*)&VS(k, tx * 2);
            ull b0, b1;
            PACK2(b0, vv.x, vv.x); PACK2(b1, vv.y, vv.y);
            FMA2(O2[0][0], a01.x, b0); FMA2(O2[0][1], a01.x, b1);
            FMA2(O2[1][0], a01.y, b0); FMA2(O2[1][1], a01.y, b1);
            FMA2(O2[2][0], a23.x, b0); FMA2(O2[2][1], a23.x, b1);
            FMA2(O2[3][0], a23.y, b0); FMA2(O2[3][1], a23.y, b1);
        }
    }

    // reduce l across tx (disjoint 4-key slices per chunk)
#pragma unroll
    for (int r = 0; r < 8; r++)
#pragma unroll
        for (int off = 8; off; off >>= 1)
            lr[r] += __shfl_xor_sync(0xffffffffu, lr[r], off);

#pragma unroll
    for (int i = 0; i < 4; i++) {
        float o0l, o0h, o1l, o1h;
        UNPACK2(o0l, o0h, O2[i][0]);
        UNPACK2(o1l, o1h, O2[i][1]);
        float inv0 = 1.f / lr[2*i+0];
        float inv1 = 1.f / lr[2*i+1];
        int qa = q0 + ty * 8 + 2*i;
        float* dst0 = &g_o[((size_t)b * NTOK + qa)     * CDIM + h * DH + tx * 2];
        float* dst1 = &g_o[((size_t)b * NTOK + qa + 1) * CDIM + h * DH + tx * 2];
        *(float2*)dst0 = make_float2(o0l * inv0, o1l * inv0);
        *(float2*)dst1 = make_float2(o0h * inv1, o1h * inv1);
    }
}

// ---------------------------------------------------------------------------
// Kernel 3: output projection + bias (R4 version).
// ---------------------------------------------------------------------------
__global__ __launch_bounds__(256) void proj_gemm(const float* __restrict__ W,
                                                 const float* __restrict__ bias,
                                                 float* __restrict__ out) {
    int b  = blockIdx.z;
    int m0 = blockIdx.x * 128;
    int o0 = blockIdx.y * 128;
    __shared__ float As[16][128];
    __shared__ float Bs[16][128];
    int t  = threadIdx.x;
    int tx = t & 15, ty = t >> 4;

    ull acc2[4][8];   // m-pairs (tx dim) x 8 o (ty dim)
#pragma unroll
    for (int i = 0; i < 4; i++)
#pragma unroll
        for (int j = 0; j < 8; j++) acc2[i][j] = 0ull;

    const float* ao = g_o + (size_t)b * NTOK * CDIM;

    for (int k0 = 0; k0 < CDIM; k0 += 16) {
        {
            int mm = t >> 1;
            int k8 = (t & 1) * 8;
            const float* src = ao + (size_t)(m0 + mm) * CDIM + k0 + k8;
            float4 a0 = *(const float4*)src;
            float4 a1 = *(const float4*)(src + 4);
            As[k8 + 0][mm] = a0.x; As[k8 + 1][mm] = a0.y;
            As[k8 + 2][mm] = a0.z; As[k8 + 3][mm] = a0.w;
            As[k8 + 4][mm] = a1.x; As[k8 + 5][mm] = a1.y;
            As[k8 + 6][mm] = a1.z; As[k8 + 7][mm] = a1.w;

            const float* ws = W + (size_t)(o0 + mm) * CDIM + k0 + k8;
            float4 w0 = *(const float4*)ws;
            float4 w1 = *(const float4*)(ws + 4);
            Bs[k8 + 0][mm] = w0.x; Bs[k8 + 1][mm] = w0.y;
            Bs[k8 + 2][mm] = w0.z; Bs[k8 + 3][mm] = w0.w;
            Bs[k8 + 4][mm] = w1.x; Bs[k8 + 5][mm] = w1.y;
            Bs[k8 + 6][mm] = w1.z; Bs[k8 + 7][mm] = w1.w;
        }
        __syncthreads();
#pragma unroll
        for (int kk = 0; kk < 16; kk++) {
            ulonglong2 a01 = *(const ulonglong2*)&As[kk][tx * 4];
            ulonglong2 a23 = *(const ulonglong2*)&As[kk][64 + tx * 4];
            ull a2[4] = {a01.x, a01.y, a23.x, a23.y};
            float4 b0 = *(const float4*)&Bs[kk][ty * 4];
            float4 b1 = *(const float4*)&Bs[kk][64 + ty * 4];
            ull b2[8];
            PACK2(b2[0], b0.x, b0.x); PACK2(b2[1], b0.y, b0.y);
            PACK2(b2[2], b0.z, b0.z); PACK2(b2[3], b0.w, b0.w);
            PACK2(b2[4], b1.x, b1.x); PACK2(b2[5], b1.y, b1.y);
            PACK2(b2[6], b1.z, b1.z); PACK2(b2[7], b1.w, b1.w);
#pragma unroll
            for (int i = 0; i < 4; i++)
#pragma unroll
                for (int j = 0; j < 8; j++) FMA2(acc2[i][j], a2[i], b2[j]);
        }
        __syncthreads();
    }

#pragma unroll
    for (int gj = 0; gj < 2; gj++)
#pragma unroll
        for (int j = 0; j < 4; j++) {
            int J = gj * 4 + j;
            int o = o0 + gj * 64 + ty * 4 + j;
            float bv = bias[o];
            float* dstrow = out + ((size_t)b * CDIM + o) * NTOK + m0;
#pragma unroll
            for (int gi = 0; gi < 2; gi++) {
                float v0l, v0h, v1l, v1h;
                UNPACK2(v0l, v0h, acc2[gi*2 + 0][J]);
                UNPACK2(v1l, v1h, acc2[gi*2 + 1][J]);
                int ml = gi * 64 + tx * 4;
                *(float4*)&dstrow[ml] = make_float4(v0l + bv, v0h + bv,
                                                    v1l + bv, v1h + bv);
            }
        }
}

// ---------------------------------------------------------------------------
extern "C" void kernel_launch(void* const* d_in, const int* in_sizes, int n_in,
                              void* d_out, int out_size) {
    const float* x     = (const float*)d_in[0];
    const float* Wqkv  = (const float*)d_in[1];
    const float* Wproj = (const float*)d_in[2];
    const float* bproj = (const float*)d_in[3];
    float* out = (float*)d_out;

    cudaFuncSetAttribute(flash_attn4,
                         cudaFuncAttributeMaxDynamicSharedMemorySize, FLASH_SMEM);

    qkv_gemm<<<dim3(8, 9, 8), 256>>>(x, Wqkv);
    flash_attn4<<<dim3(8, 12, 8), 256, FLASH_SMEM>>>();
    proj_gemm<<<dim3(8, 3, 8), 256>>>(Wproj, bproj, out);
}